// round 9
// baseline (speedup 1.0000x reference)
#include <cuda_runtime.h>
#include <cuda_bf16.h>
#include <cstdint>

#define N_Q   16384
#define DIMS  64
#define K_CB  8192
#define MT    128            // queries per CTA
#define NT    128            // codewords per tile
#define NTILES (K_CB / NT)   // 64
#define THREADS 512

#define QSCALE 21.166666f            // 127/6
#define TAU    3.0f

// padded s8 row: 64 data + 16 pad = 80 bytes (conflict-free ldmatrix, stride 80)
#define ROWB 80
#define TERM_BYTES (128 * ROWB)      // 10240 per tile
#define STAGE (TERM_BYTES + 512)     // tile + csq = 10752

// shared memory layout (bytes)
#define SM_B     0                       // 4 stages x 10752 = 43008
#define SM_A     43008                   // 10240
#define SM_CAND  53248                   // 128 q x 64 slots x 8B = 65536
#define SM_BESTK 118784                  // 128 ints
#define SMEM_TOTAL 119296

__device__ __align__(16) int8_t g_enc_s8[N_Q * DIMS];
__device__ __align__(16) int8_t g_cb_s8[K_CB * DIMS];
__device__ __align__(16) float  g_csq[K_CB];

// ---------------- helpers ----------------
__device__ __forceinline__ uint32_t smem_u32(const void* p) {
    uint32_t a;
    asm("{ .reg .u64 t; cvta.to.shared.u64 t, %1; cvt.u32.u64 %0, t; }" : "=r"(a) : "l"(p));
    return a;
}
#define CP16(d, s)  asm volatile("cp.async.cg.shared.global [%0], [%1], 16;" :: "r"(d), "l"(s))
#define CP_COMMIT() asm volatile("cp.async.commit_group;" ::: "memory")
#define CP_WAIT2()  asm volatile("cp.async.wait_group 2;" ::: "memory")

__device__ __forceinline__ void ldsm_x4(uint32_t* r, uint32_t addr) {
    asm volatile("ldmatrix.sync.aligned.m8n8.x4.shared.b16 {%0,%1,%2,%3}, [%4];"
                 : "=r"(r[0]), "=r"(r[1]), "=r"(r[2]), "=r"(r[3]) : "r"(addr));
}
__device__ __forceinline__ void imma16832(int* c, const uint32_t* a, const uint32_t* b) {
    asm volatile("mma.sync.aligned.m16n8k32.row.col.s32.s8.s8.s32 "
                 "{%0,%1,%2,%3}, {%4,%5,%6,%7}, {%8,%9}, {%0,%1,%2,%3};"
                 : "+r"(c[0]), "+r"(c[1]), "+r"(c[2]), "+r"(c[3])
                 : "r"(a[0]), "r"(a[1]), "r"(a[2]), "r"(a[3]), "r"(b[0]), "r"(b[1]));
}

// ---------------- preprocessing: quantize fp32 -> s8 ----------------
__device__ __forceinline__ int8_t q8(float v) {
    float s = fminf(fmaxf(v * QSCALE, -127.f), 127.f);
    return (int8_t)__float2int_rn(s);
}
__global__ void prep_kernel(const float* __restrict__ enc, const float* __restrict__ cb) {
    int idx = blockIdx.x * blockDim.x + threadIdx.x;     // one float4 -> 4 bytes
    const int n4e = N_Q * DIMS / 4;
    const float4* src;
    char4* dst;
    int j;
    if (idx < n4e) { src = (const float4*)enc; j = idx; dst = (char4*)g_enc_s8; }
    else           { src = (const float4*)cb;  j = idx - n4e; dst = (char4*)g_cb_s8; }
    float4 v = src[j];
    char4 o;
    o.x = q8(v.x); o.y = q8(v.y); o.z = q8(v.z); o.w = q8(v.w);
    dst[j] = o;
}

__global__ void csq_kernel(const float* __restrict__ cb) {
    int row  = blockIdx.x * 8 + (threadIdx.x >> 5);
    int lane = threadIdx.x & 31;
    float v0 = cb[row * DIMS + lane];
    float v1 = cb[row * DIMS + 32 + lane];
    float s  = v0 * v0 + v1 * v1;
    #pragma unroll
    for (int off = 16; off; off >>= 1) s += __shfl_xor_sync(0xffffffffu, s, off);
    if (lane == 0) g_csq[row] = s;
}

// ---------------- B tile loader: 128 rows x 64B = 512 x 16B chunks ----------------
__device__ __forceinline__ void load_B_tile(uint32_t smem_base, int tile, int stage, int tid) {
    const int kb = tile * NT;
    {
        int r = tid >> 2;                 // codeword row within tile
        int q = tid & 3;                  // 16B chunk
        const char* src = (const char*)g_cb_s8 + (size_t)(kb + r) * 64 + q * 16;
        uint32_t dst = smem_base + SM_B + stage * STAGE + r * ROWB + q * 16;
        CP16(dst, src);
    }
    if (tid < 32) {
        uint32_t dst = smem_base + SM_B + stage * STAGE + TERM_BYTES + tid * 16;
        CP16(dst, (const char*)g_csq + (size_t)kb * 4 + tid * 16);
    }
}

// ---------------- main kernel ----------------
__global__ __launch_bounds__(THREADS, 1)
void vq_main(const float* __restrict__ enc, const float* __restrict__ cb,
             float* __restrict__ out)
{
    extern __shared__ char smem[];
    const uint32_t smem_base = smem_u32(smem);
    const int tid  = threadIdx.x;
    const int wid  = tid >> 5;
    const int lane = tid & 31;
    const int wm   = wid & 3;             // 4 warps over M (32 rows each)
    const int wn   = wid >> 2;            // 4 warps over N (32 cols each)
    const int m0   = blockIdx.x * MT;

    // ---- start B pipeline immediately (stages 0..2) ----
    load_B_tile(smem_base, 0, 0, tid); CP_COMMIT();
    load_B_tile(smem_base, 1, 1, tid); CP_COMMIT();
    load_B_tile(smem_base, 2, 2, tid); CP_COMMIT();

    // ---- stage A (s8), padded rows: 512 x 16B chunks ----
    {
        int r = tid >> 2;
        int q = tid & 3;
        const uint4* src = (const uint4*)(g_enc_s8 + (size_t)(m0 + r) * 64) + q;
        *(uint4*)(smem + SM_A + r * ROWB + q * 16) = *src;
    }
    __syncthreads();

    // ldmatrix base addresses (16 rows x 32B coverage per x4)
    const uint32_t a_base = smem_base + SM_A
        + (wm * 32 + (lane & 15)) * ROWB + (lane >> 4) * 16;
    const uint32_t b_base0 = smem_base + SM_B
        + (wn * 32 + (lane & 15)) * ROWB + (lane >> 4) * 16;

    // ---- hoist A fragments (tile-invariant): [ks][m-tile][frag] ----
    uint32_t af[2][2][4];
    #pragma unroll
    for (int ks = 0; ks < 2; ++ks)
        #pragma unroll
        for (int i = 0; i < 2; ++i)
            ldsm_x4(af[ks][i], a_base + i * 16 * ROWB + ks * 32);

    // top-4 per owned query row (4 rows/thread), slice = 512 codewords
    float bm1[4], bm2[4], bm3[4], bm4[4];
    int   bi1[4], bi2[4], bi3[4], bi4[4];
    #pragma unroll
    for (int r = 0; r < 4; ++r) {
        bm1[r] = 3.4e38f; bm2[r] = 3.4e38f; bm3[r] = 3.4e38f; bm4[r] = 3.4e38f;
        bi1[r] = 0; bi2[r] = 0; bi3[r] = 0; bi4[r] = 0;
    }

    const float mRS2 = -2.0f / (QSCALE * QSCALE);
    int acc[2][4][4];

    for (int t = 0; t < NTILES; ++t) {
        const int stage = t & 3;
        CP_WAIT2();                       // tile t resident
        __syncthreads();                  // stage (t+3)&3 fully consumed by all warps
        if (t + 3 < NTILES) load_B_tile(smem_base, t + 3, (t + 3) & 3, tid);
        CP_COMMIT();

        #pragma unroll
        for (int i = 0; i < 2; ++i)
            #pragma unroll
            for (int j = 0; j < 4; ++j)
                #pragma unroll
                for (int r = 0; r < 4; ++r) acc[i][j][r] = 0;

        const uint32_t bs = b_base0 + stage * STAGE;
        #pragma unroll
        for (int ks = 0; ks < 2; ++ks) {
            // B fragments: 2 x ldsm.x4 cover n0-31 for this k32 chunk
            uint32_t bf[4][2];
            #pragma unroll
            for (int nt = 0; nt < 2; ++nt) {
                uint32_t r4[4];
                ldsm_x4(r4, bs + nt * 16 * ROWB + ks * 32);
                bf[nt * 2 + 0][0] = r4[0]; bf[nt * 2 + 0][1] = r4[2];
                bf[nt * 2 + 1][0] = r4[1]; bf[nt * 2 + 1][1] = r4[3];
            }
            #pragma unroll
            for (int i = 0; i < 2; ++i)
                #pragma unroll
                for (int j = 0; j < 4; ++j) imma16832(acc[i][j], af[ks][i], bf[j]);
        }

        // ---- fused argmin epilogue (top-4 per owned query row) ----
        const int kb = t * NT;
        #pragma unroll
        for (int j = 0; j < 4; ++j) {
            float2 cs = *(const float2*)(smem + SM_B + stage * STAGE + TERM_BYTES
                        + (wn * 32 + j * 8 + (lane & 3) * 2) * 4);
            const int k0 = kb + wn * 32 + j * 8 + (lane & 3) * 2;
            #pragma unroll
            for (int i = 0; i < 2; ++i) {
                #pragma unroll
                for (int h = 0; h < 2; ++h) {
                    const int ri = i * 2 + h;
                    #pragma unroll
                    for (int c = 0; c < 2; ++c) {
                        float m = fmaf((float)acc[i][j][h * 2 + c], mRS2, c ? cs.y : cs.x);
                        const int k = k0 + c;
                        if (m < bm4[ri]) {
                            if (m < bm2[ri]) {
                                if (m < bm1[ri]) {
                                    bm4[ri]=bm3[ri]; bi4[ri]=bi3[ri];
                                    bm3[ri]=bm2[ri]; bi3[ri]=bi2[ri];
                                    bm2[ri]=bm1[ri]; bi2[ri]=bi1[ri];
                                    bm1[ri]=m;       bi1[ri]=k;
                                } else {
                                    bm4[ri]=bm3[ri]; bi4[ri]=bi3[ri];
                                    bm3[ri]=bm2[ri]; bi3[ri]=bi2[ri];
                                    bm2[ri]=m;       bi2[ri]=k;
                                }
                            } else {
                                if (m < bm3[ri]) {
                                    bm4[ri]=bm3[ri]; bi4[ri]=bi3[ri];
                                    bm3[ri]=m;       bi3[ri]=k;
                                } else {
                                    bm4[ri]=m;       bi4[ri]=k;
                                }
                            }
                        }
                    }
                }
            }
        }
        // next iteration's leading sync protects stage reuse
    }

    // ---- candidate dump: 16 slices x 4 (m, k) per query ----
    __syncthreads();
    {
        float2* cand = (float2*)(smem + SM_CAND);
        const int slot = wn * 4 + (lane & 3);            // 0..15
        #pragma unroll
        for (int i = 0; i < 2; ++i)
            #pragma unroll
            for (int h = 0; h < 2; ++h) {
                const int ri = i * 2 + h;
                const int q  = wm * 32 + i * 16 + h * 8 + (lane >> 2);
                float2* p = &cand[q * 64 + slot * 4];
                p[0] = make_float2(bm1[ri], __int_as_float(bi1[ri]));
                p[1] = make_float2(bm2[ri], __int_as_float(bi2[ri]));
                p[2] = make_float2(bm3[ri], __int_as_float(bi3[ri]));
                p[3] = make_float2(bm4[ri], __int_as_float(bi4[ri]));
            }
    }
    __syncthreads();

    // ---- margin-gated exact fp32 rescore: one warp per query ----
    {
        const float2* cand = (const float2*)(smem + SM_CAND);
        int* bestk = (int*)(smem + SM_BESTK);
        for (int it = 0; it < 8; ++it) {
            const int q = wid * 8 + it;
            float2 c0 = cand[q * 64 + lane];
            float2 c1 = cand[q * 64 + 32 + lane];
            float lm = fminf(c0.x, c1.x);
            #pragma unroll
            for (int off = 16; off; off >>= 1)
                lm = fminf(lm, __shfl_xor_sync(0xffffffffu, lm, off));
            const float thresh = lm + TAU;

            const float4* er = (const float4*)(enc + (size_t)(m0 + q) * DIMS);
            float bm = 3.4e38f; int bk = 0x7fffffff;
            #pragma unroll
            for (int rnd = 0; rnd < 2; ++rnd) {
                float2 cc = rnd ? c1 : c0;
                if (cc.x <= thresh) {
                    const int k = __float_as_int(cc.y);
                    const float4* cr = (const float4*)(cb + (size_t)k * DIMS);
                    float s = 0.f;
                    #pragma unroll
                    for (int u = 0; u < 16; ++u) {
                        float4 a = er[u], b = cr[u];
                        s = fmaf(a.x, b.x, s); s = fmaf(a.y, b.y, s);
                        s = fmaf(a.z, b.z, s); s = fmaf(a.w, b.w, s);
                    }
                    float m = fmaf(-2.f, s, g_csq[k]);
                    if (m < bm || (m == bm && k < bk)) { bm = m; bk = k; }
                }
            }
            #pragma unroll
            for (int off = 16; off; off >>= 1) {
                float om = __shfl_xor_sync(0xffffffffu, bm, off);
                int   ok = __shfl_xor_sync(0xffffffffu, bk, off);
                if (om < bm || (om == bm && ok < bk)) { bm = om; bk = ok; }
            }
            if (lane == 0) bestk[q] = bk;
        }
    }
    __syncthreads();

    // ---- gather output rows ----
    {
        const int* bestk = (const int*)(smem + SM_BESTK);
        const float4* cb4 = (const float4*)cb;
        float4* out4 = (float4*)out;
        #pragma unroll
        for (int i = 0; i < 4; ++i) {
            int lin = tid + i * THREADS;            // 0..2047
            int q = lin >> 4;
            int quad = lin & 15;
            out4[(size_t)(m0 + q) * 16 + quad] = cb4[(size_t)bestk[q] * 16 + quad];
        }
    }
}

extern "C" void kernel_launch(void* const* d_in, const int* in_sizes, int n_in,
                              void* d_out, int out_size) {
    const float* enc = (const float*)d_in[0];
    const float* cb  = (const float*)d_in[1];
    if (n_in >= 2 && in_sizes[0] == K_CB * DIMS && in_sizes[1] == N_Q * DIMS) {
        enc = (const float*)d_in[1];
        cb  = (const float*)d_in[0];
    }
    float* out = (float*)d_out;

    cudaFuncSetAttribute(vq_main, cudaFuncAttributeMaxDynamicSharedMemorySize, SMEM_TOTAL);

    prep_kernel<<<(N_Q * DIMS + K_CB * DIMS) / 4 / 256, 256>>>(enc, cb);
    csq_kernel<<<K_CB / 8, 256>>>(cb);
    vq_main<<<N_Q / MT, THREADS, SMEM_TOTAL>>>(enc, cb, out);
}

// round 11
// speedup vs baseline: 1.5726x; 1.5726x over previous
#include <cuda_runtime.h>
#include <cuda_fp16.h>
#include <cstdint>

#define N_Q   16384
#define DIMS  64
#define K_CB  8192
#define MT    128            // queries per CTA
#define NT    128            // codewords per tile
#define NTILES (K_CB / NT)   // 64
#define THREADS 512

// padded f16 row: 64 elems + 8 pad = 72 elems = 144 bytes
#define ROWB 144
#define TERM_BYTES (128 * ROWB)      // 18432 per tile (128 rows)
#define STAGE (TERM_BYTES + 512)     // tile + csq = 18944
#define TAU 2.5f

// shared memory layout (bytes)
#define SM_B     0                       // 4 stages x 18944 = 75776
#define SM_A     75776                   // 18432
#define SM_CAND  94208                   // 128 q x 48 slots x 8B = 49152
#define SM_BESTK 143360                  // 128 ints
#define SMEM_TOTAL 143872

__device__ __half g_enc_h[N_Q * DIMS];
__device__ __half g_cb_h[K_CB * DIMS];
__device__ __align__(16) float g_csq[K_CB];

// ---------------- helpers ----------------
__device__ __forceinline__ uint32_t smem_u32(const void* p) {
    uint32_t a;
    asm("{ .reg .u64 t; cvta.to.shared.u64 t, %1; cvt.u32.u64 %0, t; }" : "=r"(a) : "l"(p));
    return a;
}
#define CP16(d, s)  asm volatile("cp.async.cg.shared.global [%0], [%1], 16;" :: "r"(d), "l"(s))
#define CP_COMMIT() asm volatile("cp.async.commit_group;" ::: "memory")
#define CP_WAIT2()  asm volatile("cp.async.wait_group 2;" ::: "memory")

__device__ __forceinline__ void ldsm_x4(uint32_t* r, uint32_t addr) {
    asm volatile("ldmatrix.sync.aligned.m8n8.x4.shared.b16 {%0,%1,%2,%3}, [%4];"
                 : "=r"(r[0]), "=r"(r[1]), "=r"(r[2]), "=r"(r[3]) : "r"(addr));
}
// f16 x f16 -> f16 accumulate: D/C are 2 packed f16x2 regs
__device__ __forceinline__ void mma16816_h(uint32_t* c, const uint32_t* a, const uint32_t* b) {
    asm volatile("mma.sync.aligned.m16n8k16.row.col.f16.f16.f16.f16 "
                 "{%0,%1}, {%2,%3,%4,%5}, {%6,%7}, {%0,%1};"
                 : "+r"(c[0]), "+r"(c[1])
                 : "r"(a[0]), "r"(a[1]), "r"(a[2]), "r"(a[3]), "r"(b[0]), "r"(b[1]));
}

// ---------------- preprocessing ----------------
__global__ void prep_kernel(const float* __restrict__ enc, const float* __restrict__ cb) {
    int idx = blockIdx.x * blockDim.x + threadIdx.x;     // one float4
    const int n4e = N_Q * DIMS / 4;
    const float4* src;
    __half2* ph;
    int j;
    if (idx < n4e) { src = (const float4*)enc; j = idx; ph = (__half2*)g_enc_h; }
    else           { src = (const float4*)cb;  j = idx - n4e; ph = (__half2*)g_cb_h; }
    float4 v = src[j];
    ph[j * 2]     = __floats2half2_rn(v.x, v.y);
    ph[j * 2 + 1] = __floats2half2_rn(v.z, v.w);
}

__global__ void csq_kernel(const float* __restrict__ cb) {
    int row  = blockIdx.x * 8 + (threadIdx.x >> 5);
    int lane = threadIdx.x & 31;
    float v0 = cb[row * DIMS + lane];
    float v1 = cb[row * DIMS + 32 + lane];
    float s  = v0 * v0 + v1 * v1;
    #pragma unroll
    for (int off = 16; off; off >>= 1) s += __shfl_xor_sync(0xffffffffu, s, off);
    if (lane == 0) g_csq[row] = s;
}

// ---------------- B tile loader ----------------
__device__ __forceinline__ void load_B_tile(uint32_t smem_base, int tile, int stage, int tid) {
    const int kb = tile * NT;
    #pragma unroll
    for (int i = 0; i < 2; ++i) {
        int c = tid + i * THREADS;        // 0..1023
        int r = c >> 3;                   // codeword row within tile
        int q = c & 7;                    // 16B chunk
        const char* src = (const char*)g_cb_h + (size_t)(kb + r) * 128 + q * 16;
        uint32_t dst = smem_base + SM_B + stage * STAGE + r * ROWB + q * 16;
        CP16(dst, src);
    }
    if (tid < 32) {
        uint32_t dst = smem_base + SM_B + stage * STAGE + TERM_BYTES + tid * 16;
        CP16(dst, (const char*)g_csq + (size_t)kb * 4 + tid * 16);
    }
}

// ---------------- main kernel ----------------
__global__ __launch_bounds__(THREADS, 1)
void vq_main(const float* __restrict__ enc, const float* __restrict__ cb,
             float* __restrict__ out)
{
    extern __shared__ char smem[];
    const uint32_t smem_base = smem_u32(smem);
    const int tid  = threadIdx.x;
    const int wid  = tid >> 5;
    const int lane = tid & 31;
    const int wm   = wid & 3;             // 4 warps over M (32 rows each)
    const int wn   = wid >> 2;            // 4 warps over N (32 cols each)
    const int m0   = blockIdx.x * MT;

    // ---- start B pipeline immediately (stages 0..2) ----
    load_B_tile(smem_base, 0, 0, tid); CP_COMMIT();
    load_B_tile(smem_base, 1, 1, tid); CP_COMMIT();
    load_B_tile(smem_base, 2, 2, tid); CP_COMMIT();

    // ---- stage A (f16), padded rows ----
    #pragma unroll
    for (int i = 0; i < 2; ++i) {
        int c = tid + i * THREADS;        // 0..1023
        int r = c >> 3;
        int q = c & 7;
        const uint4* src = (const uint4*)(g_enc_h + (size_t)(m0 + r) * DIMS) + q;
        *(uint4*)(smem + SM_A + r * ROWB + q * 16) = *src;
    }
    __syncthreads();

    // ldmatrix base addresses
    const uint32_t a_base = smem_base + SM_A
        + (wm * 32 + (lane & 15)) * ROWB + ((lane >> 4) & 1) * 16;
    const uint32_t b_base = smem_base + SM_B
        + (wn * 32 + (lane >> 4) * 8 + (lane & 7)) * ROWB + ((lane >> 3) & 1) * 16;

    // ---- hoist A fragments (tile-invariant): 2 m16 tiles x 4 ks ----
    uint32_t af[4][2][4];                 // [ks][i][frag]
    #pragma unroll
    for (int ks = 0; ks < 4; ++ks)
        #pragma unroll
        for (int i = 0; i < 2; ++i)
            ldsm_x4(af[ks][i], a_base + i * 16 * ROWB + ks * 32);

    // top-3 per owned query row (4 rows/thread)
    float bm1[4], bm2[4], bm3[4];
    int   bi1[4], bi2[4], bi3[4];
    #pragma unroll
    for (int r = 0; r < 4; ++r) {
        bm1[r] = 3.4e38f; bm2[r] = 3.4e38f; bm3[r] = 3.4e38f;
        bi1[r] = 0; bi2[r] = 0; bi3[r] = 0;
    }

    uint32_t acc[2][4][2];                // f16x2 packed accumulators

    for (int t = 0; t < NTILES; ++t) {
        const int stage = t & 3;
        CP_WAIT2();                       // tile t resident
        __syncthreads();                  // stage (t+3)&3 fully consumed by all warps
        if (t + 3 < NTILES) load_B_tile(smem_base, t + 3, (t + 3) & 3, tid);
        CP_COMMIT();

        #pragma unroll
        for (int i = 0; i < 2; ++i)
            #pragma unroll
            for (int j = 0; j < 4; ++j) { acc[i][j][0] = 0u; acc[i][j][1] = 0u; }

        const uint32_t bs = b_base + stage * STAGE;
        #pragma unroll
        for (int ks = 0; ks < 4; ++ks) {
            uint32_t bh[4][2];
            {
                uint32_t r0[4], r1[4];
                ldsm_x4(r0, bs + ks * 32);
                ldsm_x4(r1, bs + 16 * ROWB + ks * 32);
                bh[0][0] = r0[0]; bh[0][1] = r0[1];
                bh[1][0] = r0[2]; bh[1][1] = r0[3];
                bh[2][0] = r1[0]; bh[2][1] = r1[1];
                bh[3][0] = r1[2]; bh[3][1] = r1[3];
            }
            #pragma unroll
            for (int i = 0; i < 2; ++i)
                #pragma unroll
                for (int j = 0; j < 4; ++j) mma16816_h(acc[i][j], af[ks][i], bh[j]);
        }

        // ---- fused argmin epilogue (top-3 per owned query row) ----
        const int kb = t * NT;
        #pragma unroll
        for (int j = 0; j < 4; ++j) {
            float2 cs = *(const float2*)(smem + SM_B + stage * STAGE + TERM_BYTES
                        + (wn * 32 + j * 8 + (lane & 3) * 2) * 4);
            const int k0 = kb + wn * 32 + j * 8 + (lane & 3) * 2;
            #pragma unroll
            for (int i = 0; i < 2; ++i) {
                #pragma unroll
                for (int h = 0; h < 2; ++h) {
                    const int ri = i * 2 + h;
                    float2 dv = __half22float2(*(const __half2*)&acc[i][j][h]);
                    #pragma unroll
                    for (int c = 0; c < 2; ++c) {
                        float m = fmaf(-2.f, c ? dv.y : dv.x, c ? cs.y : cs.x);
                        const int k = k0 + c;
                        if (m < bm3[ri]) {
                            if (m < bm1[ri]) {
                                bm3[ri] = bm2[ri]; bi3[ri] = bi2[ri];
                                bm2[ri] = bm1[ri]; bi2[ri] = bi1[ri];
                                bm1[ri] = m;       bi1[ri] = k;
                            } else if (m < bm2[ri]) {
                                bm3[ri] = bm2[ri]; bi3[ri] = bi2[ri];
                                bm2[ri] = m;       bi2[ri] = k;
                            } else {
                                bm3[ri] = m;       bi3[ri] = k;
                            }
                        }
                    }
                }
            }
        }
        // next iteration's leading sync protects stage reuse
    }

    // ---- candidate dump: 16 slices x 3 (m, k) per query ----
    __syncthreads();
    {
        float2* cand = (float2*)(smem + SM_CAND);
        const int slot = wn * 4 + (lane & 3);            // 0..15
        #pragma unroll
        for (int i = 0; i < 2; ++i)
            #pragma unroll
            for (int h = 0; h < 2; ++h) {
                const int ri = i * 2 + h;
                const int q  = wm * 32 + i * 16 + h * 8 + (lane >> 2);
                float2* p = &cand[q * 48 + slot * 3];
                p[0] = make_float2(bm1[ri], __int_as_float(bi1[ri]));
                p[1] = make_float2(bm2[ri], __int_as_float(bi2[ri]));
                p[2] = make_float2(bm3[ri], __int_as_float(bi3[ri]));
            }
    }
    __syncthreads();

    // ---- margin-gated exact fp32 rescore: one warp per query ----
    {
        const float2* cand = (const float2*)(smem + SM_CAND);
        int* bestk = (int*)(smem + SM_BESTK);
        for (int it = 0; it < 8; ++it) {
            const int q = wid * 8 + it;
            float2 c0 = cand[q * 48 + lane];
            float2 c1 = (lane < 16) ? cand[q * 48 + 32 + lane]
                                    : make_float2(3.4e38f, __int_as_float(0));
            float lm = fminf(c0.x, c1.x);
            #pragma unroll
            for (int off = 16; off; off >>= 1)
                lm = fminf(lm, __shfl_xor_sync(0xffffffffu, lm, off));
            const float thresh = lm + TAU;

            const float4* er = (const float4*)(enc + (size_t)(m0 + q) * DIMS);
            float bm = 3.4e38f; int bk = 0x7fffffff;
            #pragma unroll
            for (int rnd = 0; rnd < 2; ++rnd) {
                float2 cc = rnd ? c1 : c0;
                if (cc.x <= thresh) {
                    const int k = __float_as_int(cc.y);
                    const float4* cr = (const float4*)(cb + (size_t)k * DIMS);
                    float s = 0.f;
                    #pragma unroll
                    for (int u = 0; u < 16; ++u) {
                        float4 a = er[u], b = cr[u];
                        s = fmaf(a.x, b.x, s); s = fmaf(a.y, b.y, s);
                        s = fmaf(a.z, b.z, s); s = fmaf(a.w, b.w, s);
                    }
                    float m = fmaf(-2.f, s, g_csq[k]);
                    if (m < bm || (m == bm && k < bk)) { bm = m; bk = k; }
                }
            }
            #pragma unroll
            for (int off = 16; off; off >>= 1) {
                float om = __shfl_xor_sync(0xffffffffu, bm, off);
                int   ok = __shfl_xor_sync(0xffffffffu, bk, off);
                if (om < bm || (om == bm && ok < bk)) { bm = om; bk = ok; }
            }
            if (lane == 0) bestk[q] = bk;
        }
    }
    __syncthreads();

    // ---- gather output rows ----
    {
        const int* bestk = (const int*)(smem + SM_BESTK);
        const float4* cb4 = (const float4*)cb;
        float4* out4 = (float4*)out;
        #pragma unroll
        for (int i = 0; i < 4; ++i) {
            int lin = tid + i * THREADS;            // 0..2047
            int q = lin >> 4;
            int quad = lin & 15;
            out4[(size_t)(m0 + q) * 16 + quad] = cb4[(size_t)bestk[q] * 16 + quad];
        }
    }
}

extern "C" void kernel_launch(void* const* d_in, const int* in_sizes, int n_in,
                              void* d_out, int out_size) {
    const float* enc = (const float*)d_in[0];
    const float* cb  = (const float*)d_in[1];
    if (n_in >= 2 && in_sizes[0] == K_CB * DIMS && in_sizes[1] == N_Q * DIMS) {
        enc = (const float*)d_in[1];
        cb  = (const float*)d_in[0];
    }
    float* out = (float*)d_out;

    cudaFuncSetAttribute(vq_main, cudaFuncAttributeMaxDynamicSharedMemorySize, SMEM_TOTAL);

    prep_kernel<<<(N_Q * DIMS + K_CB * DIMS) / 4 / 256, 256>>>(enc, cb);
    csq_kernel<<<K_CB / 8, 256>>>(cb);
    vq_main<<<N_Q / MT, THREADS, SMEM_TOTAL>>>(enc, cb, out);
}